// round 2
// baseline (speedup 1.0000x reference)
#include <cuda_runtime.h>

#define BATCH 16
#define NA 3
#define NC 80
#define HH 76
#define WW 76
#define HW (HH * WW)
#define TOTAL (BATCH * NA * HW)
#define BOXES_ELEMS (TOTAL * 4)

__global__ __launch_bounds__(256) void yolo_decode_kernel(
    const float* __restrict__ in, float* __restrict__ out)
{
    int t = blockIdx.x * blockDim.x + threadIdx.x;
    if (t >= TOTAL) return;

    int ba  = t / HW;          // b*NA + a
    int pos = t - ba * HW;     // h*W + w
    int a   = ba % NA;

    const float* __restrict__ p = in + (size_t)ba * (5 + NC) * HW + pos;

    // head channels
    float tx = p[0 * HW];
    float ty = p[1 * HW];
    float tw = p[2 * HW];
    float th = p[3 * HW];
    float tc = p[4 * HW];

    // class logits — batched coalesced loads, kept in registers
    float cls[NC];
#pragma unroll
    for (int c = 0; c < NC; c++) cls[c] = p[(5 + c) * HW];

    // max-stabilized softmax
    float m = cls[0];
#pragma unroll
    for (int c = 1; c < NC; c++) m = fmaxf(m, cls[c]);
    float s = 0.f;
#pragma unroll
    for (int c = 0; c < NC; c++) {
        cls[c] = __expf(cls[c] - m);
        s += cls[c];
    }

    float det   = __fdividef(1.f, 1.f + __expf(-tc));   // sigmoid(conf)
    float scale = __fdividef(det, s);                   // det / sum(exp)

    // box decode
    int gx = pos % WW;
    int gy = pos / WW;
    float sx = __fdividef(1.f, 1.f + __expf(-tx));
    float sy = __fdividef(1.f, 1.f + __expf(-ty));
    float bx = (sx + (float)gx) * (1.0f / WW);
    float by = (sy + (float)gy) * (1.0f / HH);

    // anchors / stride(=8) / grid: w: {12,19,40}/8/76   h: {16,36,28}/8/76
    const float awW[NA] = {1.5f / WW, 2.375f / WW, 5.0f / WW};
    const float ahH[NA] = {2.0f / HH, 4.5f  / HH, 3.5f / HH};
    float bw = __expf(tw) * awW[a];
    float bh = __expf(th) * ahH[a];

    // boxes: (B, A*H*W, 4) — row index == t
    float4* __restrict__ boxes = (float4*)out;
    boxes[t] = make_float4(bx, by, bw, bh);

    // confs: (B, A*H*W, 80) — 320 contiguous bytes per thread
    float4* __restrict__ confs =
        (float4*)(out + (size_t)BOXES_ELEMS + (size_t)t * NC);
#pragma unroll
    for (int c = 0; c < NC; c += 4) {
        confs[c >> 2] = make_float4(cls[c] * scale, cls[c + 1] * scale,
                                    cls[c + 2] * scale, cls[c + 3] * scale);
    }
}

extern "C" void kernel_launch(void* const* d_in, const int* in_sizes, int n_in,
                              void* d_out, int out_size)
{
    const float* in = (const float*)d_in[0];
    float* out = (float*)d_out;
    int blocks = (TOTAL + 255) / 256;
    yolo_decode_kernel<<<blocks, 256>>>(in, out);
}

// round 3
// speedup vs baseline: 1.0156x; 1.0156x over previous
#include <cuda_runtime.h>

#define BATCH 16
#define NA 3
#define NC 80
#define HH 76
#define WW 76
#define HW (HH * WW)
#define TOTAL (BATCH * NA * HW)
#define BOXES_ELEMS (TOTAL * 4)

__global__ __launch_bounds__(256) void yolo_decode_kernel(
    const float* __restrict__ in, float* __restrict__ out)
{
    int t = blockIdx.x * blockDim.x + threadIdx.x;
    if (t >= TOTAL) return;

    int ba  = t / HW;          // b*NA + a
    int pos = t - ba * HW;     // h*W + w
    int a   = ba % NA;

    const float* __restrict__ p = in + (size_t)ba * (5 + NC) * HW + pos;

    // head channels
    float tx = p[0 * HW];
    float ty = p[1 * HW];
    float tw = p[2 * HW];
    float th = p[3 * HW];
    float tc = p[4 * HW];

    // class logits — batched coalesced loads, kept in registers
    float cls[NC];
#pragma unroll
    for (int c = 0; c < NC; c++) cls[c] = p[(5 + c) * HW];

    // max-stabilized softmax
    float m = cls[0];
#pragma unroll
    for (int c = 1; c < NC; c++) m = fmaxf(m, cls[c]);
    float s = 0.f;
#pragma unroll
    for (int c = 0; c < NC; c++) {
        cls[c] = __expf(cls[c] - m);
        s += cls[c];
    }

    float det   = __fdividef(1.f, 1.f + __expf(-tc));   // sigmoid(conf)
    float scale = __fdividef(det, s);                   // det / sum(exp)

    // box decode
    int gx = pos % WW;
    int gy = pos / WW;
    float sx = __fdividef(1.f, 1.f + __expf(-tx));
    float sy = __fdividef(1.f, 1.f + __expf(-ty));
    float bx = (sx + (float)gx) * (1.0f / WW);
    float by = (sy + (float)gy) * (1.0f / HH);

    // anchors / stride(=8) / grid: w: {12,19,40}/8/76   h: {16,36,28}/8/76
    const float awW[NA] = {1.5f / WW, 2.375f / WW, 5.0f / WW};
    const float ahH[NA] = {2.0f / HH, 4.5f  / HH, 3.5f / HH};
    float bw = __expf(tw) * awW[a];
    float bh = __expf(th) * ahH[a];

    // boxes: (B, A*H*W, 4) — row index == t
    float4* __restrict__ boxes = (float4*)out;
    boxes[t] = make_float4(bx, by, bw, bh);

    // confs: (B, A*H*W, 80) — 320 contiguous bytes per thread
    float4* __restrict__ confs =
        (float4*)(out + (size_t)BOXES_ELEMS + (size_t)t * NC);
#pragma unroll
    for (int c = 0; c < NC; c += 4) {
        confs[c >> 2] = make_float4(cls[c] * scale, cls[c + 1] * scale,
                                    cls[c + 2] * scale, cls[c + 3] * scale);
    }
}

extern "C" void kernel_launch(void* const* d_in, const int* in_sizes, int n_in,
                              void* d_out, int out_size)
{
    const float* in = (const float*)d_in[0];
    float* out = (float*)d_out;
    int blocks = (TOTAL + 255) / 256;
    yolo_decode_kernel<<<blocks, 256>>>(in, out);
}